// round 3
// baseline (speedup 1.0000x reference)
#include <cuda_runtime.h>
#include <stdint.h>

// ---------------------------------------------------------------------------
// Problem constants
// ---------------------------------------------------------------------------
#define B_ 64
#define S_ 400
#define E_ 512
#define H_ 1024
#define A_ 512
#define V_ 50257
#define SB_ (S_ * B_)   // 25600

// Output layout: flat concat of (logits, h1, c1, attn_weights, input_feed_new)
#define O_LOGITS ((size_t)0)
#define O_H1     ((size_t)B_ * V_)
#define O_C1     (O_H1 + (size_t)B_ * H_)
#define O_ATTN   (O_C1 + (size_t)B_ * H_)
#define O_IFN    (O_ATTN + (size_t)SB_)

// ---------------------------------------------------------------------------
// Device scratch (static only — no cudaMalloc allowed)
// ---------------------------------------------------------------------------
__device__ float g_x[B_ * (E_ + H_)];          // [64,1536]
__device__ float g_gp[5 * B_ * 4 * H_];        // gate GEMM split-K partials
__device__ float g_qp[8 * B_ * A_];            // query split-K partials
__device__ float g_query[B_ * A_];             // [64,512]
__device__ float g_ifp[4 * B_ * H_];           // lin_out split-K partials
__device__ float g_alignp[2 * SB_];            // per-Nblock align partials
__device__ float g_cat[B_ * 2 * H_];           // [64,2048] h1 | ctx

// ---------------------------------------------------------------------------
// PTX helpers
// ---------------------------------------------------------------------------
__device__ __forceinline__ void cp16(uint32_t dst, const void* src, int szbytes) {
    asm volatile("cp.async.cg.shared.global [%0], [%1], 16, %2;\n"
                 :: "r"(dst), "l"(src), "r"(szbytes));
}
__device__ __forceinline__ void cp16f(uint32_t dst, const void* src) {
    asm volatile("cp.async.cg.shared.global [%0], [%1], 16;\n"
                 :: "r"(dst), "l"(src));
}
__device__ __forceinline__ void cp_commit() {
    asm volatile("cp.async.commit_group;\n");
}
template <int N>
__device__ __forceinline__ void cp_wait() {
    asm volatile("cp.async.wait_group %0;\n" :: "n"(N));
}
__device__ __forceinline__ uint32_t tf32_of(float v) {
    uint32_t u;
    asm("cvt.rna.tf32.f32 %0, %1;" : "=r"(u) : "f"(v));
    return u;
}
__device__ __forceinline__ float tanh_fast(float x) {
    float y;
    asm("tanh.approx.f32 %0, %1;" : "=f"(y) : "f"(x));
    return y;
}
__device__ __forceinline__ void mma_tf32(float* d, const uint32_t* a, const uint32_t* b) {
    asm volatile(
        "mma.sync.aligned.m16n8k8.row.col.f32.tf32.tf32.f32 "
        "{%0,%1,%2,%3}, {%4,%5,%6,%7}, {%8,%9}, {%0,%1,%2,%3};\n"
        : "+f"(d[0]), "+f"(d[1]), "+f"(d[2]), "+f"(d[3])
        : "r"(a[0]), "r"(a[1]), "r"(a[2]), "r"(a[3]),
          "r"(b[0]), "r"(b[1]));
}

#define BK 32
#define PAD 36   // BK + 4

// ---------------------------------------------------------------------------
// Small TN GEMM: C[64,N] = A[64,K] @ B[N,K]^T (+bias). 3-stage cp.async.
// BM=64, BN=128, 8 warps as 2(M)x4(N), warp tile 32x32.
// Split-K via blockIdx.z (slice z -> C + z*64*N). Dual source: blocks with
// z >= zsplit read (A2, lda2, B2, ldb2) with local slice index z-zsplit.
// ---------------------------------------------------------------------------
__global__ __launch_bounds__(256, 2)
void gemm_small(const float* __restrict__ A, int lda,
                const float* __restrict__ Bw, int ldb,
                float* __restrict__ C, int N, int klen,
                const float* __restrict__ bias,
                const float* __restrict__ A2, int lda2,
                const float* __restrict__ B2, int ldb2, int zsplit)
{
    extern __shared__ float smem[];
    float* As = smem;                    // [3][64][PAD]
    float* Bs = smem + 3 * 64 * PAD;     // [3][128][PAD]

    const int tid  = threadIdx.x;
    const int wid  = tid >> 5;
    const int lane = tid & 31;
    const int wm   = wid >> 2;
    const int wn   = wid & 3;
    const int g    = lane >> 2;
    const int tg   = lane & 3;
    const int bn0  = blockIdx.x * 128;

    const float* Asel = A;  int ldaS = lda;
    const float* Bsel = Bw; int ldbS = ldb;
    int zz = blockIdx.z;
    if (zz >= zsplit) { Asel = A2; ldaS = lda2; Bsel = B2; ldbS = ldb2; zz -= zsplit; }
    const int kbase = zz * klen;

    const uint32_t sA = (uint32_t)__cvta_generic_to_shared(As);
    const uint32_t sB = (uint32_t)__cvta_generic_to_shared(Bs);

    float acc[2][4][4];
#pragma unroll
    for (int mt = 0; mt < 2; mt++)
#pragma unroll
        for (int nt = 0; nt < 4; nt++)
#pragma unroll
            for (int e = 0; e < 4; e++) acc[mt][nt][e] = 0.f;

    auto load_stage = [&](int st, int kt0) {
        {
            const int idx = tid;           // A: 64 rows x 8 chunks = 512 -> 2/thr
            const int r = idx >> 3;
            const int kc = (idx & 7) * 4;
            cp16f(sA + ((st * 64 + r) * PAD + kc) * 4,
                  Asel + (size_t)r * ldaS + kbase + kt0 + kc);
        }
        {
            const int idx = tid + 256;
            const int r = idx >> 3;
            const int kc = (idx & 7) * 4;
            cp16f(sA + ((st * 64 + r) * PAD + kc) * 4,
                  Asel + (size_t)r * ldaS + kbase + kt0 + kc);
        }
#pragma unroll
        for (int i = 0; i < 4; i++) {     // B: 128 rows x 8 = 1024 -> 4/thr
            const int idx = tid + i * 256;
            const int r = idx >> 3;
            const int kc = (idx & 7) * 4;
            cp16(sB + ((st * 128 + r) * PAD + kc) * 4,
                 Bsel + (size_t)(bn0 + r) * ldbS + kbase + kt0 + kc,
                 (bn0 + r) < N ? 16 : 0);
        }
    };

    const int NKT = klen / BK;
    load_stage(0, 0);            cp_commit();
    load_stage(1, BK);           cp_commit();

    for (int kt = 0; kt < NKT; kt++) {
        cp_wait<1>();
        __syncthreads();
        if (kt + 2 < NKT) load_stage((kt + 2) % 3, (kt + 2) * BK);
        cp_commit();

        const int st = kt % 3;
        const float* Ab = As + (size_t)(st * 64 + wm * 32) * PAD;
        const float* Bb = Bs + (size_t)(st * 128 + wn * 32) * PAD;
#pragma unroll
        for (int kk = 0; kk < BK; kk += 8) {
            uint32_t af[2][4];
            uint32_t bf[4][2];
#pragma unroll
            for (int mt = 0; mt < 2; mt++) {
                const float* p = Ab + mt * 16 * PAD + kk;
                af[mt][0] = tf32_of(p[(g)     * PAD + tg]);
                af[mt][1] = tf32_of(p[(g + 8) * PAD + tg]);
                af[mt][2] = tf32_of(p[(g)     * PAD + tg + 4]);
                af[mt][3] = tf32_of(p[(g + 8) * PAD + tg + 4]);
            }
#pragma unroll
            for (int nt = 0; nt < 4; nt++) {
                const float* p = Bb + nt * 8 * PAD + kk;
                bf[nt][0] = tf32_of(p[g * PAD + tg]);
                bf[nt][1] = tf32_of(p[g * PAD + tg + 4]);
            }
#pragma unroll
            for (int mt = 0; mt < 2; mt++)
#pragma unroll
                for (int nt = 0; nt < 4; nt++)
                    mma_tf32(acc[mt][nt], af[mt], bf[nt]);
        }
    }

    float* Cout = C + (size_t)blockIdx.z * 64 * N;
#pragma unroll
    for (int mt = 0; mt < 2; mt++) {
#pragma unroll
        for (int nt = 0; nt < 4; nt++) {
#pragma unroll
            for (int e = 0; e < 4; e++) {
                const int r = wm * 32 + mt * 16 + g + (e >> 1) * 8;
                const int c = bn0 + wn * 32 + nt * 8 + 2 * tg + (e & 1);
                if (c < N) {
                    float v = acc[mt][nt][e];
                    if (bias) v += bias[c];
                    Cout[(size_t)r * N + c] = v;
                }
            }
        }
    }
}

// ---------------------------------------------------------------------------
// Keys GEMM fused with Bahdanau align epilogue.
// [25600,512] = enc[25600,1024] @ attnm_w[512,1024]^T
// BM=128, BN=256, 8 warps as 2(M)x4(N), warp tile 64x64 (1 LDS per MMA).
// 3-stage cp.async. Epilogue:
//   alignp[blockIdx.x*SB + row] = sum_c align_w[c]*tanh(acc[row][c]+query[row&63][c])
// ---------------------------------------------------------------------------
__global__ __launch_bounds__(256, 1)
void gemm_keys(const float* __restrict__ enc,
               const float* __restrict__ attnm_w,
               const float* __restrict__ query,
               const float* __restrict__ align_w,
               float* __restrict__ alignp)
{
    extern __shared__ float smem[];
    float* As = smem;                    // [3][128][PAD]
    float* Bs = smem + 3 * 128 * PAD;    // [3][256][PAD]

    const int tid  = threadIdx.x;
    const int wid  = tid >> 5;
    const int lane = tid & 31;
    const int wm   = wid >> 2;
    const int wn   = wid & 3;
    const int g    = lane >> 2;
    const int tg   = lane & 3;
    const int bn0  = blockIdx.x * 256;
    const int bm0  = blockIdx.y * 128;

    const uint32_t sA = (uint32_t)__cvta_generic_to_shared(As);
    const uint32_t sB = (uint32_t)__cvta_generic_to_shared(Bs);

    float acc[4][8][4];
#pragma unroll
    for (int mt = 0; mt < 4; mt++)
#pragma unroll
        for (int nt = 0; nt < 8; nt++)
#pragma unroll
            for (int e = 0; e < 4; e++) acc[mt][nt][e] = 0.f;

    auto load_stage = [&](int st, int kt0) {
#pragma unroll
        for (int i = 0; i < 4; i++) {    // A: 128 rows x 8 = 1024 -> 4/thr
            const int idx = tid + i * 256;
            const int r = idx >> 3;
            const int kc = (idx & 7) * 4;
            cp16f(sA + ((st * 128 + r) * PAD + kc) * 4,
                  enc + (size_t)(bm0 + r) * H_ + kt0 + kc);
        }
#pragma unroll
        for (int i = 0; i < 8; i++) {    // B: 256 rows x 8 = 2048 -> 8/thr
            const int idx = tid + i * 256;
            const int r = idx >> 3;
            const int kc = (idx & 7) * 4;
            cp16f(sB + ((st * 256 + r) * PAD + kc) * 4,
                  attnm_w + (size_t)(bn0 + r) * H_ + kt0 + kc);
        }
    };

    const int NKT = H_ / BK;             // 32
    load_stage(0, 0);  cp_commit();
    load_stage(1, BK); cp_commit();

    for (int kt = 0; kt < NKT; kt++) {
        cp_wait<1>();
        __syncthreads();
        if (kt + 2 < NKT) load_stage((kt + 2) % 3, (kt + 2) * BK);
        cp_commit();

        const int st = kt % 3;
        const float* Ab = As + (size_t)(st * 128 + wm * 64) * PAD;
        const float* Bb = Bs + (size_t)(st * 256 + wn * 64) * PAD;
#pragma unroll
        for (int kk = 0; kk < BK; kk += 8) {
            uint32_t af[4][4];
            uint32_t bf[8][2];
#pragma unroll
            for (int mt = 0; mt < 4; mt++) {
                const float* p = Ab + mt * 16 * PAD + kk;
                af[mt][0] = tf32_of(p[(g)     * PAD + tg]);
                af[mt][1] = tf32_of(p[(g + 8) * PAD + tg]);
                af[mt][2] = tf32_of(p[(g)     * PAD + tg + 4]);
                af[mt][3] = tf32_of(p[(g + 8) * PAD + tg + 4]);
            }
#pragma unroll
            for (int nt = 0; nt < 8; nt++) {
                const float* p = Bb + nt * 8 * PAD + kk;
                bf[nt][0] = tf32_of(p[g * PAD + tg]);
                bf[nt][1] = tf32_of(p[g * PAD + tg + 4]);
            }
#pragma unroll
            for (int mt = 0; mt < 4; mt++)
#pragma unroll
                for (int nt = 0; nt < 8; nt++)
                    mma_tf32(acc[mt][nt], af[mt], bf[nt]);
        }
    }

    // Epilogue: per-row partial over this block's 256 N-cols.
    float rs[4][2];
#pragma unroll
    for (int mt = 0; mt < 4; mt++) { rs[mt][0] = 0.f; rs[mt][1] = 0.f; }
#pragma unroll
    for (int mt = 0; mt < 4; mt++) {
#pragma unroll
        for (int nt = 0; nt < 8; nt++) {
#pragma unroll
            for (int e = 0; e < 4; e++) {
                const int rloc = wm * 64 + mt * 16 + g + (e >> 1) * 8;
                const int c = bn0 + wn * 64 + nt * 8 + 2 * tg + (e & 1);
                const int b = (bm0 + rloc) & (B_ - 1);
                const float t = tanh_fast(acc[mt][nt][e] + query[b * A_ + c]);
                rs[mt][e >> 1] += align_w[c] * t;
            }
        }
    }
#pragma unroll
    for (int mt = 0; mt < 4; mt++) {
#pragma unroll
        for (int hh = 0; hh < 2; hh++) {
            float v = rs[mt][hh];
            v += __shfl_xor_sync(0xffffffffu, v, 1);
            v += __shfl_xor_sync(0xffffffffu, v, 2);
            rs[mt][hh] = v;
        }
    }
    __syncthreads();
    float* red = smem;                   // [128][4]
    if (tg == 0) {
#pragma unroll
        for (int mt = 0; mt < 4; mt++) {
#pragma unroll
            for (int hh = 0; hh < 2; hh++) {
                const int rloc = wm * 64 + mt * 16 + g + hh * 8;
                red[rloc * 4 + wn] = rs[mt][hh];
            }
        }
    }
    __syncthreads();
    if (tid < 128) {
        const float s = red[tid * 4] + red[tid * 4 + 1] +
                        red[tid * 4 + 2] + red[tid * 4 + 3];
        alignp[(size_t)blockIdx.x * SB_ + bm0 + tid] = s;
    }
}

// ---------------------------------------------------------------------------
// Small kernels
// ---------------------------------------------------------------------------
__global__ void build_x_kernel(const int* __restrict__ tokens,
                               const float* __restrict__ emb_table,
                               const float* __restrict__ input_feed)
{
    const int b = blockIdx.x;
    const float* erow = emb_table + (size_t)tokens[b] * E_;
    for (int j = threadIdx.x; j < E_ + H_; j += blockDim.x)
        g_x[b * (E_ + H_) + j] = (j < E_) ? erow[j] : input_feed[b * H_ + (j - E_)];
}

__device__ __forceinline__ float4 f4add(float4 a, float4 b) {
    return make_float4(a.x + b.x, a.y + b.y, a.z + b.z, a.w + b.w);
}

// Reduce 5 gate partial slices + biases, apply LSTM cell (float4).
__global__ void lstm_kernel(const float* __restrict__ c0,
                            const float* __restrict__ b_ih,
                            const float* __restrict__ b_hh,
                            float* __restrict__ h1, float* __restrict__ c1)
{
    const int t = blockIdx.x * 256 + threadIdx.x;   // 0..16383
    const int i4 = t * 4;
    const int b = i4 >> 10;
    const int h = i4 & 1023;
    float4 gi = f4add(*(const float4*)&b_ih[h],           *(const float4*)&b_hh[h]);
    float4 gf = f4add(*(const float4*)&b_ih[H_ + h],      *(const float4*)&b_hh[H_ + h]);
    float4 gg = f4add(*(const float4*)&b_ih[2 * H_ + h],  *(const float4*)&b_hh[2 * H_ + h]);
    float4 go = f4add(*(const float4*)&b_ih[3 * H_ + h],  *(const float4*)&b_hh[3 * H_ + h]);
#pragma unroll
    for (int z = 0; z < 5; z++) {
        const float* p = g_gp + (size_t)z * B_ * 4 * H_ + (size_t)b * 4 * H_;
        gi = f4add(gi, *(const float4*)&p[h]);
        gf = f4add(gf, *(const float4*)&p[H_ + h]);
        gg = f4add(gg, *(const float4*)&p[2 * H_ + h]);
        go = f4add(go, *(const float4*)&p[3 * H_ + h]);
    }
    const float4 cin = *(const float4*)&c0[i4];
    float cc[4], hh[4];
    const float giv[4] = {gi.x, gi.y, gi.z, gi.w};
    const float gfv[4] = {gf.x, gf.y, gf.z, gf.w};
    const float ggv[4] = {gg.x, gg.y, gg.z, gg.w};
    const float gov[4] = {go.x, go.y, go.z, go.w};
    const float cv[4]  = {cin.x, cin.y, cin.z, cin.w};
#pragma unroll
    for (int j = 0; j < 4; j++) {
        const float si = 1.f / (1.f + expf(-giv[j]));
        const float sf = 1.f / (1.f + expf(-gfv[j]));
        const float so = 1.f / (1.f + expf(-gov[j]));
        cc[j] = sf * cv[j] + si * tanhf(ggv[j]);
        hh[j] = so * tanhf(cc[j]);
    }
    *(float4*)&c1[i4] = make_float4(cc[0], cc[1], cc[2], cc[3]);
    const float4 h4 = make_float4(hh[0], hh[1], hh[2], hh[3]);
    *(float4*)&h1[i4] = h4;
    *(float4*)&g_cat[b * 2 * H_ + h] = h4;
}

__global__ void qreduce_kernel(const float* __restrict__ attnq_b)
{
    const int t = blockIdx.x * 256 + threadIdx.x;   // 0..8191
    const int i4 = t * 4;
    const int c = i4 & (A_ - 1);
    float4 s = *(const float4*)&attnq_b[c];
#pragma unroll
    for (int z = 0; z < 8; z++)
        s = f4add(s, *(const float4*)&g_qp[(size_t)z * B_ * A_ + i4]);
    *(float4*)&g_query[i4] = s;
}

__global__ void ifreduce_kernel(const float* __restrict__ lin_out_b,
                                float* __restrict__ out_ifn)
{
    const int t = blockIdx.x * 256 + threadIdx.x;   // 0..16383
    const int i4 = t * 4;
    const int c = i4 & (H_ - 1);
    float4 s = *(const float4*)&lin_out_b[c];
#pragma unroll
    for (int z = 0; z < 4; z++)
        s = f4add(s, *(const float4*)&g_ifp[(size_t)z * B_ * H_ + i4]);
    *(float4*)&out_ifn[i4] = s;
}

// softmax over s for each batch column; alignment = sum of 2 N-block partials
__global__ void softmax_kernel(float* __restrict__ w)
{
    __shared__ float vals[S_];
    __shared__ float red[128];
    const int b = blockIdx.x;
    const int tid = threadIdx.x;
    for (int s = tid; s < S_; s += 128)
        vals[s] = g_alignp[s * B_ + b] + g_alignp[SB_ + s * B_ + b];
    __syncthreads();
    float m = -1e30f;
    for (int s = tid; s < S_; s += 128) m = fmaxf(m, vals[s]);
    red[tid] = m; __syncthreads();
    for (int o = 64; o; o >>= 1) {
        if (tid < o) red[tid] = fmaxf(red[tid], red[tid + o]);
        __syncthreads();
    }
    m = red[0]; __syncthreads();
    float sum = 0.f;
    for (int s = tid; s < S_; s += 128) sum += expf(vals[s] - m);
    red[tid] = sum; __syncthreads();
    for (int o = 64; o; o >>= 1) {
        if (tid < o) red[tid] += red[tid + o];
        __syncthreads();
    }
    const float inv = 1.f / red[0];
    for (int s = tid; s < S_; s += 128)
        w[s * B_ + b] = expf(vals[s] - m) * inv;
}

// ctx[b,h] = sum_s w[s,b] * enc[s,b,h] -> right half of g_cat (float4)
__global__ void ctx_kernel(const float* __restrict__ w, const float* __restrict__ enc)
{
    __shared__ float ws[S_];
    const int b = blockIdx.x;
    for (int s = threadIdx.x; s < S_; s += 128) ws[s] = w[s * B_ + b];
    __syncthreads();
    const int h = (blockIdx.y * 128 + threadIdx.x) * 4;
    const float* base = enc + (size_t)b * H_ + h;
    float4 acc = make_float4(0.f, 0.f, 0.f, 0.f);
#pragma unroll 4
    for (int s = 0; s < S_; s++) {
        const float4 v = *(const float4*)(base + (size_t)s * (B_ * H_));
        const float wv = ws[s];
        acc.x += wv * v.x; acc.y += wv * v.y;
        acc.z += wv * v.z; acc.w += wv * v.w;
    }
    *(float4*)&g_cat[b * 2 * H_ + H_ + h] = acc;
}

// ---------------------------------------------------------------------------
// kernel_launch
// ---------------------------------------------------------------------------
extern "C" void kernel_launch(void* const* d_in, const int* in_sizes, int n_in,
                              void* d_out, int out_size)
{
    (void)in_sizes; (void)n_in; (void)out_size;
    const int*   tokens     = (const int*)  d_in[0];
    const float* h0         = (const float*)d_in[1];
    const float* c0         = (const float*)d_in[2];
    const float* enc        = (const float*)d_in[3];
    const float* input_feed = (const float*)d_in[4];
    const float* emb_table  = (const float*)d_in[5];
    const float* W_ih       = (const float*)d_in[6];
    const float* W_hh       = (const float*)d_in[7];
    const float* b_ih       = (const float*)d_in[8];
    const float* b_hh       = (const float*)d_in[9];
    const float* attnm_w    = (const float*)d_in[10];
    const float* attnq_w    = (const float*)d_in[11];
    const float* attnq_b    = (const float*)d_in[12];
    const float* align_w    = (const float*)d_in[13];
    const float* lin_out_w  = (const float*)d_in[14];
    const float* lin_out_b  = (const float*)d_in[15];
    const float* out_w      = (const float*)d_in[16];
    const float* out_b      = (const float*)d_in[17];

    float* out = (float*)d_out;
    float* out_logits = out + O_LOGITS;
    float* out_h1     = out + O_H1;
    float* out_c1     = out + O_C1;
    float* out_attn   = out + O_ATTN;
    float* out_ifn    = out + O_IFN;

    float *x, *gp, *qp, *query, *ifp, *alignp, *cat;
    cudaGetSymbolAddress((void**)&x,      g_x);
    cudaGetSymbolAddress((void**)&gp,     g_gp);
    cudaGetSymbolAddress((void**)&qp,     g_qp);
    cudaGetSymbolAddress((void**)&query,  g_query);
    cudaGetSymbolAddress((void**)&ifp,    g_ifp);
    cudaGetSymbolAddress((void**)&alignp, g_alignp);
    cudaGetSymbolAddress((void**)&cat,    g_cat);

    const int smemS = 3 * (64 + 128) * PAD * 4;    // 82944
    const int smemK = 3 * (128 + 256) * PAD * 4;   // 165888
    cudaFuncSetAttribute((const void*)gemm_small,
                         cudaFuncAttributeMaxDynamicSharedMemorySize, smemS);
    cudaFuncSetAttribute((const void*)gemm_keys,
                         cudaFuncAttributeMaxDynamicSharedMemorySize, smemK);

    // 1. x = [emb | input_feed]
    build_x_kernel<<<B_, 256>>>(tokens, emb_table, input_feed);

    // 2. gates partials: z 0..2 = x@W_ih^T (K=1536), z 3..4 = h0@W_hh^T (K=1024)
    gemm_small<<<dim3(32, 1, 5), 256, smemS>>>(
        x, E_ + H_, W_ih, E_ + H_, gp, 4 * H_, 512, nullptr,
        h0, H_, W_hh, H_, 3);

    // 3. gate reduce + LSTM cell
    lstm_kernel<<<64, 256>>>(c0, b_ih, b_hh, out_h1, out_c1);

    // 4. query partials (8 K-slices) + reduce
    gemm_small<<<dim3(4, 1, 8), 256, smemS>>>(
        out_h1, H_, attnq_w, H_, qp, A_, 128, nullptr,
        nullptr, 0, nullptr, 0, 1000);
    qreduce_kernel<<<32, 256>>>(attnq_b);

    // 5. keys GEMM fused with align epilogue
    gemm_keys<<<dim3(2, SB_ / 128), 256, smemK>>>(
        enc, attnm_w, query, align_w, alignp);

    // 6. softmax over s
    softmax_kernel<<<B_, 128>>>(out_attn);

    // 7. context
    ctx_kernel<<<dim3(B_, 2), 128>>>(out_attn, enc);

    // 8. input_feed_new partials (4 K-slices) + reduce
    gemm_small<<<dim3(8, 1, 4), 256, smemS>>>(
        cat, 2 * H_, lin_out_w, 2 * H_, ifp, H_, 512, nullptr,
        nullptr, 0, nullptr, 0, 1000);
    ifreduce_kernel<<<64, 256>>>(lin_out_b, out_ifn);

    // 9. logits
    gemm_small<<<dim3((V_ + 127) / 128, 1, 1), 256, smemS>>>(
        out_ifn, H_, out_w, H_, out_logits, V_, H_, out_b,
        nullptr, 0, nullptr, 0, 1000);
}